// round 13
// baseline (speedup 1.0000x reference)
#include <cuda_runtime.h>
#include <cuda_fp16.h>
#include <cuda_bf16.h>
#include <math.h>

#define NN 100000
#define EE 1600000
#define TEC (EE + NN)
#define BIGF 1e30f

// ---------------- scratch ----------------
__device__ __half2 g_h1h[NN * 32];   // h1 fp16: 64 cols = 32 half2
__device__ __half2 g_h2h[NN * 20];   // h2 fp16: 40 cols = 20 half2
__device__ float   g_a1s[NN * 8];
__device__ float   g_a1d[NN * 8];
__device__ float   g_a2s[NN];
__device__ float   g_a2d[NN];
__device__ int     g_counts[NN];
__device__ int     g_rowptr[NN + 1];
__device__ int     g_csr[TEC];
__device__ int     g_bsum[128];
__device__ int     g_scanctr;
__device__ int     g_flag;

// ------- zero counts + reset scan barrier + edge dtype detection (fused) -----
__global__ void k_initdet(const unsigned* __restrict__ u, int N) {
    if (blockIdx.x == 0) {
        if (threadIdx.x < 32) {
            unsigned v = 0;
            for (int j = threadIdx.x; j < 128; j += 32) v |= u[2 * j + 1];
            unsigned any = __ballot_sync(0xffffffffu, v != 0u);
            if (threadIdx.x == 0) { g_flag = (any == 0u) ? 1 : 0; g_scanctr = 0; }
        }
    }
    int i = blockIdx.x * blockDim.x + threadIdx.x;
    if (i < N) g_counts[i] = 0;
}

// ---------------- histogram over dst ----------------
__global__ void k_hist(const void* __restrict__ ei, int E) {
    int idx = blockIdx.x * blockDim.x + threadIdx.x;
    if (idx * 2 >= E) return;
    int d0, d1;
    if (g_flag) {
        const longlong2* p = (const longlong2*)ei;
        longlong2 dv = p[(E >> 1) + idx];
        d0 = (int)dv.x; d1 = (int)dv.y;
    } else {
        const int2* p = (const int2*)ei;
        int2 dv = p[(E >> 1) + idx];
        d0 = dv.x; d1 = dv.y;
    }
    atomicAdd(&g_counts[d0], 1);
    atomicAdd(&g_counts[d1], 1);
}

// -------- single-pass scan: counts(+1 self loop) -> exclusive rowptr ---------
// grid = NB (<=98) blocks x 1024 threads: single wave, safe device-wide spin.
__global__ void k_scan(int N, int NB) {
    __shared__ int sm[1024];
    __shared__ int red[32];
    __shared__ int sbase;
    int t = threadIdx.x, b = blockIdx.x;
    int i = b * 1024 + t;
    int v = (i < N) ? (g_counts[i] + 1) : 0;   // +1 = self-loop
    sm[t] = v;
    __syncthreads();
    for (int off = 1; off < 1024; off <<= 1) {
        int u = (t >= off) ? sm[t - off] : 0;
        __syncthreads();
        sm[t] += u;
        __syncthreads();
    }
    int incl = sm[t];
    if (t == 1023) {
        g_bsum[b] = incl;          // block total
        __threadfence();
        atomicAdd(&g_scanctr, 1);
    }
    // wait for all block totals
    if (t == 0) {
        while (atomicAdd(&g_scanctr, 0) < NB) { }
    }
    __syncthreads();
    __threadfence();
    // base = sum of totals of preceding blocks (parallel reduce)
    int part = (t < b) ? g_bsum[t] : 0;
#pragma unroll
    for (int o = 16; o; o >>= 1) part += __shfl_xor_sync(0xffffffffu, part, o);
    if ((t & 31) == 0) red[t >> 5] = part;
    __syncthreads();
    if (t < 32) {
        int p2 = red[t];
#pragma unroll
        for (int o = 16; o; o >>= 1) p2 += __shfl_xor_sync(0xffffffffu, p2, o);
        if (t == 0) sbase = p2;
    }
    __syncthreads();
    int excl = sbase + incl - v;
    if (i < N) g_rowptr[i] = excl;
    if (i == N - 1) g_rowptr[N] = excl + v;
}

// ------ scatter: atomicAdd on rowptr itself; rowptr[d] becomes segment end ---
__global__ void k_scatter(const void* __restrict__ ei, int E, int N) {
    int e = blockIdx.x * blockDim.x + threadIdx.x;
    if (e >= E + N) return;
    int s, d;
    if (e < E) {
        if (g_flag) {
            const long long* p = (const long long*)ei;
            s = (int)p[e]; d = (int)p[E + e];
        } else {
            const int* p = (const int*)ei;
            s = p[e]; d = p[E + e];
        }
    } else { s = e - E; d = s; }
    int pos = atomicAdd(&g_rowptr[d], 1);
    g_csr[pos] = s;
}

// ---------------- GEMM1: bf16 tensor-core, 128x64 tile, fused att epilogue ---
#define SA 72   // As row stride (bf16)
#define SB 72   // Bs row stride (bf16)
#define SC 68   // Cs row stride (fp32)

__global__ void __launch_bounds__(256)
k_gemm1(const float* __restrict__ x, const float* __restrict__ W,
        const float* __restrict__ as1, const float* __restrict__ ad1, int N) {
    __shared__ __align__(16) unsigned char smem[128 * SC * 4];  // 34816 B
    __nv_bfloat16* As = (__nv_bfloat16*)smem;                 // [128][SA]
    __nv_bfloat16* Bs = (__nv_bfloat16*)(smem + 128 * SA * 2);// [64][SB]
    float* Cs = (float*)smem;                                 // [128][SC]

    int t = threadIdx.x;
    int lane = t & 31, warp = t >> 5;
    int wm = warp & 3, wn = warp >> 2;
    int r0 = blockIdx.x * 128;

    float d[2][4][4];
#pragma unroll
    for (int mi = 0; mi < 2; ++mi)
#pragma unroll
        for (int ni = 0; ni < 4; ++ni)
#pragma unroll
            for (int j = 0; j < 4; ++j) d[mi][ni][j] = 0.f;

    for (int kt = 0; kt < 2; ++kt) {
#pragma unroll
        for (int p = 0; p < 8; ++p) {
            int idx4 = t + p * 256;
            int row = idx4 >> 4;
            int kq = idx4 & 15;
            int gr = r0 + row;
            float4 v = make_float4(0.f, 0.f, 0.f, 0.f);
            if (gr < N) v = *(const float4*)&x[(size_t)gr * 128 + kt * 64 + kq * 4];
            __nv_bfloat162 lo = __floats2bfloat162_rn(v.x, v.y);
            __nv_bfloat162 hi = __floats2bfloat162_rn(v.z, v.w);
            uint2 pk = make_uint2(*(unsigned*)&lo, *(unsigned*)&hi);
            *(uint2*)&As[row * SA + kq * 4] = pk;
        }
#pragma unroll
        for (int p = 0; p < 4; ++p) {
            int idx4 = t + p * 256;
            int row = idx4 >> 4;
            int nq = idx4 & 15;
            float4 v = *(const float4*)&W[(size_t)(kt * 64 + row) * 64 + nq * 4];
            __nv_bfloat162 lo = __floats2bfloat162_rn(v.x, v.y);
            __nv_bfloat162 hi = __floats2bfloat162_rn(v.z, v.w);
            uint2 pk = make_uint2(*(unsigned*)&lo, *(unsigned*)&hi);
            *(uint2*)&Bs[row * SB + nq * 4] = pk;
        }
        __syncthreads();
#pragma unroll
        for (int ks = 0; ks < 4; ++ks) {
            int k0 = ks * 16;
            unsigned a[2][4], b[4][2];
#pragma unroll
            for (int mi = 0; mi < 2; ++mi) {
                int row = wm * 32 + mi * 16 + (lane & 15);
                int col = k0 + (lane >> 4) * 8;
                unsigned sa = (unsigned)__cvta_generic_to_shared(&As[row * SA + col]);
                asm volatile("ldmatrix.sync.aligned.m8n8.x4.shared.b16 {%0,%1,%2,%3}, [%4];"
                             : "=r"(a[mi][0]), "=r"(a[mi][1]), "=r"(a[mi][2]), "=r"(a[mi][3])
                             : "r"(sa));
            }
#pragma unroll
            for (int ci = 0; ci < 2; ++ci) {
                int krow = k0 + (lane & 15);
                int col = wn * 32 + ci * 16 + (lane >> 4) * 8;
                unsigned sb = (unsigned)__cvta_generic_to_shared(&Bs[krow * SB + col]);
                unsigned q0, q1, q2, q3;
                asm volatile("ldmatrix.sync.aligned.m8n8.x4.trans.shared.b16 {%0,%1,%2,%3}, [%4];"
                             : "=r"(q0), "=r"(q1), "=r"(q2), "=r"(q3)
                             : "r"(sb));
                b[ci * 2][0] = q0; b[ci * 2][1] = q1;
                b[ci * 2 + 1][0] = q2; b[ci * 2 + 1][1] = q3;
            }
#pragma unroll
            for (int mi = 0; mi < 2; ++mi)
#pragma unroll
                for (int ni = 0; ni < 4; ++ni)
                    asm volatile(
                        "mma.sync.aligned.m16n8k16.row.col.f32.bf16.bf16.f32 "
                        "{%0,%1,%2,%3}, {%4,%5,%6,%7}, {%8,%9}, {%0,%1,%2,%3};"
                        : "+f"(d[mi][ni][0]), "+f"(d[mi][ni][1]),
                          "+f"(d[mi][ni][2]), "+f"(d[mi][ni][3])
                        : "r"(a[mi][0]), "r"(a[mi][1]), "r"(a[mi][2]), "r"(a[mi][3]),
                          "r"(b[ni][0]), "r"(b[ni][1]));
        }
        __syncthreads();
    }
    {
        int g = lane >> 2, tig = lane & 3;
#pragma unroll
        for (int mi = 0; mi < 2; ++mi)
#pragma unroll
            for (int ni = 0; ni < 4; ++ni) {
                int rb = wm * 32 + mi * 16 + g;
                int c = wn * 32 + ni * 8 + 2 * tig;
                Cs[rb * SC + c]       = d[mi][ni][0];
                Cs[rb * SC + c + 1]   = d[mi][ni][1];
                Cs[(rb + 8) * SC + c]     = d[mi][ni][2];
                Cs[(rb + 8) * SC + c + 1] = d[mi][ni][3];
            }
    }
    __syncthreads();
    int tx = t & 15, ty = t >> 4;
    float4 asv = *(const float4*)&as1[tx * 4];
    float4 adv = *(const float4*)&ad1[tx * 4];
#pragma unroll
    for (int rr = 0; rr < 8; ++rr) {
        int row = ty + rr * 16;
        int gr = r0 + row;
        float4 c = *(const float4*)&Cs[row * SC + tx * 4];
        float ps = c.x * asv.x + c.y * asv.y + c.z * asv.z + c.w * asv.w;
        float pd = c.x * adv.x + c.y * adv.y + c.z * adv.z + c.w * adv.w;
        ps += __shfl_xor_sync(0xffffffffu, ps, 1);
        pd += __shfl_xor_sync(0xffffffffu, pd, 1);
        if (gr < N) {
            g_h1h[(size_t)gr * 32 + tx * 2]     = __floats2half2_rn(c.x, c.y);
            g_h1h[(size_t)gr * 32 + tx * 2 + 1] = __floats2half2_rn(c.z, c.w);
            if (!(tx & 1)) {
                g_a1s[(size_t)gr * 8 + (tx >> 1)] = ps;
                g_a1d[(size_t)gr * 8 + (tx >> 1)] = pd;
            }
        }
    }
}

// ------- layer-1 agg + bias + ELU + FUSED GEMM2 + att2 scalars ---------------
__global__ void __launch_bounds__(256)
k_agg1g2(const float* __restrict__ b1, const float* __restrict__ W2,
         const float* __restrict__ as2, const float* __restrict__ ad2, int N) {
    __shared__ float W2s[64 * 40];     // 10240 B
    __shared__ float sa[40], sd[40];
    __shared__ float rows[8][64];      // one out1 row per warp
    int t = threadIdx.x;
    int warp = t >> 5;
    int lane = t & 31;

    for (int i = t; i < 64 * 40; i += 256) W2s[i] = W2[i];
    if (t < 40) { sa[t] = as2[t]; sd[t] = ad2[t]; }
    __syncthreads();

    int d = blockIdx.x * 8 + warp;
    if (d >= N) return;
    int rs = (d == 0) ? 0 : __ldg(&g_rowptr[d - 1]);   // rowptr shifted by scatter
    int re = __ldg(&g_rowptr[d]);
    int h = lane & 7;
    int hsel = lane >> 2;
    float adst = g_a1d[(size_t)d * 8 + h];

    float wsum = 0.f, acc0 = 0.f, acc1 = 0.f;
    int i = rs;
    for (; i + 1 < re; i += 2) {
        int s0 = __ldg(&g_csr[i]);
        int s1 = __ldg(&g_csr[i + 1]);
        float e0 = __ldg(&g_a1s[(size_t)s0 * 8 + h]) + adst;
        float e1 = __ldg(&g_a1s[(size_t)s1 * 8 + h]) + adst;
        e0 = (e0 > 0.f) ? e0 : 0.2f * e0;
        e1 = (e1 > 0.f) ? e1 : 0.2f * e1;
        float w0 = __expf(e0);
        float w1 = __expf(e1);
        wsum += w0 + w1;
        float wa0 = __shfl_sync(0xffffffffu, w0, hsel);
        float wa1 = __shfl_sync(0xffffffffu, w1, hsel);
        float2 f0 = __half22float2(__ldg(&g_h1h[(size_t)s0 * 32 + lane]));
        float2 f1 = __half22float2(__ldg(&g_h1h[(size_t)s1 * 32 + lane]));
        acc0 += wa0 * f0.x + wa1 * f1.x;
        acc1 += wa0 * f0.y + wa1 * f1.y;
    }
    if (i < re) {
        int s = __ldg(&g_csr[i]);
        float e = __ldg(&g_a1s[(size_t)s * 8 + h]) + adst;
        e = (e > 0.f) ? e : 0.2f * e;
        float w = __expf(e);
        wsum += w;
        float wa = __shfl_sync(0xffffffffu, w, hsel);
        float2 f = __half22float2(__ldg(&g_h1h[(size_t)s * 32 + lane]));
        acc0 += wa * f.x;
        acc1 += wa * f.y;
    }
    float dsum = __shfl_sync(0xffffffffu, wsum, hsel);
    float inv = 1.f / dsum;
    float o0 = acc0 * inv + b1[2 * lane];
    float o1 = acc1 * inv + b1[2 * lane + 1];
    o0 = (o0 > 0.f) ? o0 : (__expf(o0) - 1.f);
    o1 = (o1 > 0.f) ? o1 : (__expf(o1) - 1.f);
    rows[warp][2 * lane]     = o0;
    rows[warp][2 * lane + 1] = o1;
    __syncwarp();

    // fused GEMM2: this warp's row (64) x W2 (64x40) -> 2 cols per lane (<20)
    float r0 = 0.f, r1 = 0.f;
    if (lane < 20) {
        int c = 2 * lane;
#pragma unroll 8
        for (int k = 0; k < 64; ++k) {
            float a = rows[warp][k];
            r0 += a * W2s[k * 40 + c];
            r1 += a * W2s[k * 40 + c + 1];
        }
    }
    float ps = 0.f, pd = 0.f;
    if (lane < 20) {
        ps = r0 * sa[2 * lane] + r1 * sa[2 * lane + 1];
        pd = r0 * sd[2 * lane] + r1 * sd[2 * lane + 1];
        g_h2h[(size_t)d * 20 + lane] = __floats2half2_rn(r0, r1);
    }
#pragma unroll
    for (int o = 16; o; o >>= 1) {
        ps += __shfl_xor_sync(0xffffffffu, ps, o);
        pd += __shfl_xor_sync(0xffffffffu, pd, o);
    }
    if (lane == 0) { g_a2s[d] = ps; g_a2d[d] = pd; }
}

// ---------------- layer-2 softmax + aggregation + log_softmax (2-unroll) -----
__global__ void k_agg2(const float* __restrict__ b2, float* __restrict__ out, int N) {
    int warp = threadIdx.x >> 5, lane = threadIdx.x & 31;
    int d = blockIdx.x * 8 + warp;
    if (d >= N) return;
    int rs = (d == 0) ? 0 : __ldg(&g_rowptr[d - 1]);
    int re = __ldg(&g_rowptr[d]);
    float adst = g_a2d[d];
    bool act = (lane < 20);

    float wsum = 0.f, acc0 = 0.f, acc1 = 0.f;
    int i = rs;
    for (; i + 1 < re; i += 2) {
        int s0 = __ldg(&g_csr[i]);
        int s1 = __ldg(&g_csr[i + 1]);
        float e0 = __ldg(&g_a2s[s0]) + adst;
        float e1 = __ldg(&g_a2s[s1]) + adst;
        e0 = (e0 > 0.f) ? e0 : 0.2f * e0;
        e1 = (e1 > 0.f) ? e1 : 0.2f * e1;
        float w0 = __expf(e0);
        float w1 = __expf(e1);
        wsum += w0 + w1;
        if (act) {
            float2 f0 = __half22float2(__ldg(&g_h2h[(size_t)s0 * 20 + lane]));
            float2 f1 = __half22float2(__ldg(&g_h2h[(size_t)s1 * 20 + lane]));
            acc0 += w0 * f0.x + w1 * f1.x;
            acc1 += w0 * f0.y + w1 * f1.y;
        }
    }
    if (i < re) {
        int s = __ldg(&g_csr[i]);
        float e = __ldg(&g_a2s[s]) + adst;
        e = (e > 0.f) ? e : 0.2f * e;
        float w = __expf(e);
        wsum += w;
        if (act) {
            float2 f = __half22float2(__ldg(&g_h2h[(size_t)s * 20 + lane]));
            acc0 += w * f.x;
            acc1 += w * f.y;
        }
    }
    float inv = 1.f / wsum;
    float v0 = act ? (acc0 * inv + b2[2 * lane]) : -BIGF;
    float v1 = act ? (acc1 * inv + b2[2 * lane + 1]) : -BIGF;

    float mm = fmaxf(v0, v1);
    for (int o = 16; o; o >>= 1) mm = fmaxf(mm, __shfl_xor_sync(0xffffffffu, mm, o));
    float se = act ? (__expf(v0 - mm) + __expf(v1 - mm)) : 0.f;
    for (int o = 16; o; o >>= 1) se += __shfl_xor_sync(0xffffffffu, se, o);
    float ls = mm + logf(se);
    if (act)
        *(float2*)&out[(size_t)d * 40 + 2 * lane] = make_float2(v0 - ls, v1 - ls);
}

// ---------------- launch ----------------
extern "C" void kernel_launch(void* const* d_in, const int* in_sizes, int n_in,
                              void* d_out, int out_size) {
    const float* x   = (const float*)d_in[0];
    const void*  ei  = d_in[1];
    const float* W1  = (const float*)d_in[2];
    const float* as1 = (const float*)d_in[3];
    const float* ad1 = (const float*)d_in[4];
    const float* b1  = (const float*)d_in[5];
    const float* W2  = (const float*)d_in[6];
    const float* as2 = (const float*)d_in[7];
    const float* ad2 = (const float*)d_in[8];
    const float* b2  = (const float*)d_in[9];
    float* out = (float*)d_out;

    int N = in_sizes[0] / 128;
    int E = in_sizes[1] / 2;
    int NB = (N + 1023) / 1024;

    // side stream + events (created once, on the first — non-captured — call)
    static cudaStream_t s2 = nullptr;
    static cudaEvent_t evFork = nullptr, evJoin = nullptr;
    if (!s2) {
        cudaStreamCreateWithFlags(&s2, cudaStreamNonBlocking);
        cudaEventCreateWithFlags(&evFork, cudaEventDisableTiming);
        cudaEventCreateWithFlags(&evJoin, cudaEventDisableTiming);
    }

    // fork: gemm1 runs concurrently with the CSR build chain
    cudaEventRecord(evFork, 0);
    cudaStreamWaitEvent(s2, evFork, 0);
    k_gemm1<<<(N + 127) / 128, 256, 0, s2>>>(x, W1, as1, ad1, N);
    cudaEventRecord(evJoin, s2);

    // CSR build chain on the main (capture) stream
    k_initdet<<<(N + 255) / 256, 256>>>((const unsigned*)ei, N);
    k_hist<<<(E / 2 + 255) / 256, 256>>>(ei, E);
    k_scan<<<NB, 1024>>>(N, NB);
    k_scatter<<<(E + N + 255) / 256, 256>>>(ei, E, N);

    // join: aggregation needs both CSR and gemm1 outputs
    cudaStreamWaitEvent(0, evJoin, 0);
    k_agg1g2<<<(N + 7) / 8, 256>>>(b1, W2, as2, ad2, N);
    k_agg2<<<(N + 7) / 8, 256>>>(b2, out, N);
}

// round 17
// speedup vs baseline: 1.0214x; 1.0214x over previous
#include <cuda_runtime.h>
#include <cuda_fp16.h>
#include <cuda_bf16.h>
#include <math.h>

#define NN 100000
#define EE 1600000
#define TEC (EE + NN)
#define BIGF 1e30f
#define FULLM 0xffffffffu

// ---------------- scratch ----------------
__device__ __half2 g_h1h[NN * 32];   // h1 fp16: 64 cols = 32 half2
__device__ __half2 g_h2h[NN * 20];   // h2 fp16: 40 cols = 20 half2
__device__ float   g_a1s[NN * 8];
__device__ float   g_a1d[NN * 8];
__device__ float   g_a2s[NN];
__device__ float   g_a2d[NN];
__device__ int     g_counts[NN];
__device__ int     g_rowptr[NN + 1];
__device__ int     g_csr[TEC];
__device__ int     g_bsum[128];
__device__ int     g_scanctr;
__device__ int     g_flag;

// ------- zero counts + reset scan barrier + edge dtype detection (fused) -----
__global__ void k_initdet(const unsigned* __restrict__ u, int N) {
    if (blockIdx.x == 0) {
        if (threadIdx.x < 32) {
            unsigned v = 0;
            for (int j = threadIdx.x; j < 128; j += 32) v |= u[2 * j + 1];
            unsigned any = __ballot_sync(FULLM, v != 0u);
            if (threadIdx.x == 0) { g_flag = (any == 0u) ? 1 : 0; g_scanctr = 0; }
        }
    }
    int i = blockIdx.x * blockDim.x + threadIdx.x;
    if (i < N) g_counts[i] = 0;
}

// ---------------- histogram over dst ----------------
__global__ void k_hist(const void* __restrict__ ei, int E) {
    int idx = blockIdx.x * blockDim.x + threadIdx.x;
    if (idx * 2 >= E) return;
    int d0, d1;
    if (g_flag) {
        const longlong2* p = (const longlong2*)ei;
        longlong2 dv = p[(E >> 1) + idx];
        d0 = (int)dv.x; d1 = (int)dv.y;
    } else {
        const int2* p = (const int2*)ei;
        int2 dv = p[(E >> 1) + idx];
        d0 = dv.x; d1 = dv.y;
    }
    atomicAdd(&g_counts[d0], 1);
    atomicAdd(&g_counts[d1], 1);
}

// -------- single-pass scan: counts(+1 self loop) -> exclusive rowptr ---------
__global__ void k_scan(int N, int NB) {
    __shared__ int sm[1024];
    __shared__ int red[32];
    __shared__ int sbase;
    int t = threadIdx.x, b = blockIdx.x;
    int i = b * 1024 + t;
    int v = (i < N) ? (g_counts[i] + 1) : 0;   // +1 = self-loop
    sm[t] = v;
    __syncthreads();
    for (int off = 1; off < 1024; off <<= 1) {
        int u = (t >= off) ? sm[t - off] : 0;
        __syncthreads();
        sm[t] += u;
        __syncthreads();
    }
    int incl = sm[t];
    if (t == 1023) {
        g_bsum[b] = incl;
        __threadfence();
        atomicAdd(&g_scanctr, 1);
    }
    if (t == 0) {
        while (atomicAdd(&g_scanctr, 0) < NB) { }
    }
    __syncthreads();
    __threadfence();
    int part = (t < b) ? g_bsum[t] : 0;
#pragma unroll
    for (int o = 16; o; o >>= 1) part += __shfl_xor_sync(FULLM, part, o);
    if ((t & 31) == 0) red[t >> 5] = part;
    __syncthreads();
    if (t < 32) {
        int p2 = red[t];
#pragma unroll
        for (int o = 16; o; o >>= 1) p2 += __shfl_xor_sync(FULLM, p2, o);
        if (t == 0) sbase = p2;
    }
    __syncthreads();
    int excl = sbase + incl - v;
    if (i < N) g_rowptr[i] = excl;
    if (i == N - 1) g_rowptr[N] = excl + v;
}

// ------ scatter: atomicAdd on rowptr itself; rowptr[d] becomes segment end ---
__global__ void k_scatter(const void* __restrict__ ei, int E, int N) {
    int e = blockIdx.x * blockDim.x + threadIdx.x;
    if (e >= E + N) return;
    int s, d;
    if (e < E) {
        if (g_flag) {
            const long long* p = (const long long*)ei;
            s = (int)p[e]; d = (int)p[E + e];
        } else {
            const int* p = (const int*)ei;
            s = p[e]; d = p[E + e];
        }
    } else { s = e - E; d = s; }
    int pos = atomicAdd(&g_rowptr[d], 1);
    g_csr[pos] = s;
}

// ---------------- GEMM1: bf16 tensor-core, 128x64 tile, fused att epilogue ---
#define SA 72
#define SB 72
#define SC 68

__global__ void __launch_bounds__(256)
k_gemm1(const float* __restrict__ x, const float* __restrict__ W,
        const float* __restrict__ as1, const float* __restrict__ ad1, int N) {
    __shared__ __align__(16) unsigned char smem[128 * SC * 4];
    __nv_bfloat16* As = (__nv_bfloat16*)smem;
    __nv_bfloat16* Bs = (__nv_bfloat16*)(smem + 128 * SA * 2);
    float* Cs = (float*)smem;

    int t = threadIdx.x;
    int lane = t & 31, warp = t >> 5;
    int wm = warp & 3, wn = warp >> 2;
    int r0 = blockIdx.x * 128;

    float d[2][4][4];
#pragma unroll
    for (int mi = 0; mi < 2; ++mi)
#pragma unroll
        for (int ni = 0; ni < 4; ++ni)
#pragma unroll
            for (int j = 0; j < 4; ++j) d[mi][ni][j] = 0.f;

    for (int kt = 0; kt < 2; ++kt) {
#pragma unroll
        for (int p = 0; p < 8; ++p) {
            int idx4 = t + p * 256;
            int row = idx4 >> 4;
            int kq = idx4 & 15;
            int gr = r0 + row;
            float4 v = make_float4(0.f, 0.f, 0.f, 0.f);
            if (gr < N) v = *(const float4*)&x[(size_t)gr * 128 + kt * 64 + kq * 4];
            __nv_bfloat162 lo = __floats2bfloat162_rn(v.x, v.y);
            __nv_bfloat162 hi = __floats2bfloat162_rn(v.z, v.w);
            uint2 pk = make_uint2(*(unsigned*)&lo, *(unsigned*)&hi);
            *(uint2*)&As[row * SA + kq * 4] = pk;
        }
#pragma unroll
        for (int p = 0; p < 4; ++p) {
            int idx4 = t + p * 256;
            int row = idx4 >> 4;
            int nq = idx4 & 15;
            float4 v = *(const float4*)&W[(size_t)(kt * 64 + row) * 64 + nq * 4];
            __nv_bfloat162 lo = __floats2bfloat162_rn(v.x, v.y);
            __nv_bfloat162 hi = __floats2bfloat162_rn(v.z, v.w);
            uint2 pk = make_uint2(*(unsigned*)&lo, *(unsigned*)&hi);
            *(uint2*)&Bs[row * SB + nq * 4] = pk;
        }
        __syncthreads();
#pragma unroll
        for (int ks = 0; ks < 4; ++ks) {
            int k0 = ks * 16;
            unsigned a[2][4], b[4][2];
#pragma unroll
            for (int mi = 0; mi < 2; ++mi) {
                int row = wm * 32 + mi * 16 + (lane & 15);
                int col = k0 + (lane >> 4) * 8;
                unsigned sa = (unsigned)__cvta_generic_to_shared(&As[row * SA + col]);
                asm volatile("ldmatrix.sync.aligned.m8n8.x4.shared.b16 {%0,%1,%2,%3}, [%4];"
                             : "=r"(a[mi][0]), "=r"(a[mi][1]), "=r"(a[mi][2]), "=r"(a[mi][3])
                             : "r"(sa));
            }
#pragma unroll
            for (int ci = 0; ci < 2; ++ci) {
                int krow = k0 + (lane & 15);
                int col = wn * 32 + ci * 16 + (lane >> 4) * 8;
                unsigned sb = (unsigned)__cvta_generic_to_shared(&Bs[krow * SB + col]);
                unsigned q0, q1, q2, q3;
                asm volatile("ldmatrix.sync.aligned.m8n8.x4.trans.shared.b16 {%0,%1,%2,%3}, [%4];"
                             : "=r"(q0), "=r"(q1), "=r"(q2), "=r"(q3)
                             : "r"(sb));
                b[ci * 2][0] = q0; b[ci * 2][1] = q1;
                b[ci * 2 + 1][0] = q2; b[ci * 2 + 1][1] = q3;
            }
#pragma unroll
            for (int mi = 0; mi < 2; ++mi)
#pragma unroll
                for (int ni = 0; ni < 4; ++ni)
                    asm volatile(
                        "mma.sync.aligned.m16n8k16.row.col.f32.bf16.bf16.f32 "
                        "{%0,%1,%2,%3}, {%4,%5,%6,%7}, {%8,%9}, {%0,%1,%2,%3};"
                        : "+f"(d[mi][ni][0]), "+f"(d[mi][ni][1]),
                          "+f"(d[mi][ni][2]), "+f"(d[mi][ni][3])
                        : "r"(a[mi][0]), "r"(a[mi][1]), "r"(a[mi][2]), "r"(a[mi][3]),
                          "r"(b[ni][0]), "r"(b[ni][1]));
        }
        __syncthreads();
    }
    {
        int g = lane >> 2, tig = lane & 3;
#pragma unroll
        for (int mi = 0; mi < 2; ++mi)
#pragma unroll
            for (int ni = 0; ni < 4; ++ni) {
                int rb = wm * 32 + mi * 16 + g;
                int c = wn * 32 + ni * 8 + 2 * tig;
                Cs[rb * SC + c]       = d[mi][ni][0];
                Cs[rb * SC + c + 1]   = d[mi][ni][1];
                Cs[(rb + 8) * SC + c]     = d[mi][ni][2];
                Cs[(rb + 8) * SC + c + 1] = d[mi][ni][3];
            }
    }
    __syncthreads();
    int tx = t & 15, ty = t >> 4;
    float4 asv = *(const float4*)&as1[tx * 4];
    float4 adv = *(const float4*)&ad1[tx * 4];
#pragma unroll
    for (int rr = 0; rr < 8; ++rr) {
        int row = ty + rr * 16;
        int gr = r0 + row;
        float4 c = *(const float4*)&Cs[row * SC + tx * 4];
        float ps = c.x * asv.x + c.y * asv.y + c.z * asv.z + c.w * asv.w;
        float pd = c.x * adv.x + c.y * adv.y + c.z * adv.z + c.w * adv.w;
        ps += __shfl_xor_sync(FULLM, ps, 1);
        pd += __shfl_xor_sync(FULLM, pd, 1);
        if (gr < N) {
            g_h1h[(size_t)gr * 32 + tx * 2]     = __floats2half2_rn(c.x, c.y);
            g_h1h[(size_t)gr * 32 + tx * 2 + 1] = __floats2half2_rn(c.z, c.w);
            if (!(tx & 1)) {
                g_a1s[(size_t)gr * 8 + (tx >> 1)] = ps;
                g_a1d[(size_t)gr * 8 + (tx >> 1)] = pd;
            }
        }
    }
}

// ------- layer-1 agg (shfl-indexed, 4-unroll) + ELU + FUSED GEMM2 ------------
__global__ void __launch_bounds__(256)
k_agg1g2(const float* __restrict__ b1, const float* __restrict__ W2,
         const float* __restrict__ as2, const float* __restrict__ ad2, int N) {
    __shared__ float W2s[64 * 40];
    __shared__ float sa[40], sd[40];
    __shared__ float rows[8][64];
    int t = threadIdx.x;
    int warp = t >> 5;
    int lane = t & 31;

    for (int i = t; i < 64 * 40; i += 256) W2s[i] = W2[i];
    if (t < 40) { sa[t] = as2[t]; sd[t] = ad2[t]; }
    __syncthreads();

    int d = blockIdx.x * 8 + warp;
    if (d >= N) return;
    int rs = (d == 0) ? 0 : __ldg(&g_rowptr[d - 1]);
    int re = __ldg(&g_rowptr[d]);
    int h = lane & 7;
    int hsel = lane >> 2;
    float adst = g_a1d[(size_t)d * 8 + h];

    float wsum = 0.f, acc0 = 0.f, acc1 = 0.f;

    for (int base = rs; base < re; base += 32) {
        int cnt = re - base; if (cnt > 32) cnt = 32;
        int nidx = __ldg(&g_csr[base + ((lane < cnt) ? lane : 0)]);
        int j = 0;
        for (; j + 3 < cnt; j += 4) {
            int s0 = __shfl_sync(FULLM, nidx, j);
            int s1 = __shfl_sync(FULLM, nidx, j + 1);
            int s2 = __shfl_sync(FULLM, nidx, j + 2);
            int s3 = __shfl_sync(FULLM, nidx, j + 3);
            float e0 = __ldg(&g_a1s[(size_t)s0 * 8 + h]) + adst;
            float e1 = __ldg(&g_a1s[(size_t)s1 * 8 + h]) + adst;
            float e2 = __ldg(&g_a1s[(size_t)s2 * 8 + h]) + adst;
            float e3 = __ldg(&g_a1s[(size_t)s3 * 8 + h]) + adst;
            float2 f0 = __half22float2(__ldg(&g_h1h[(size_t)s0 * 32 + lane]));
            float2 f1 = __half22float2(__ldg(&g_h1h[(size_t)s1 * 32 + lane]));
            float2 f2 = __half22float2(__ldg(&g_h1h[(size_t)s2 * 32 + lane]));
            float2 f3 = __half22float2(__ldg(&g_h1h[(size_t)s3 * 32 + lane]));
            e0 = (e0 > 0.f) ? e0 : 0.2f * e0;
            e1 = (e1 > 0.f) ? e1 : 0.2f * e1;
            e2 = (e2 > 0.f) ? e2 : 0.2f * e2;
            e3 = (e3 > 0.f) ? e3 : 0.2f * e3;
            float w0 = __expf(e0), w1 = __expf(e1), w2 = __expf(e2), w3 = __expf(e3);
            wsum += (w0 + w1) + (w2 + w3);
            float wa0 = __shfl_sync(FULLM, w0, hsel);
            float wa1 = __shfl_sync(FULLM, w1, hsel);
            float wa2 = __shfl_sync(FULLM, w2, hsel);
            float wa3 = __shfl_sync(FULLM, w3, hsel);
            acc0 += wa0 * f0.x + wa1 * f1.x + wa2 * f2.x + wa3 * f3.x;
            acc1 += wa0 * f0.y + wa1 * f1.y + wa2 * f2.y + wa3 * f3.y;
        }
        for (; j < cnt; ++j) {
            int s = __shfl_sync(FULLM, nidx, j);
            float e = __ldg(&g_a1s[(size_t)s * 8 + h]) + adst;
            float2 f = __half22float2(__ldg(&g_h1h[(size_t)s * 32 + lane]));
            e = (e > 0.f) ? e : 0.2f * e;
            float w = __expf(e);
            wsum += w;
            float wa = __shfl_sync(FULLM, w, hsel);
            acc0 += wa * f.x;
            acc1 += wa * f.y;
        }
    }
    float dsum = __shfl_sync(FULLM, wsum, hsel);
    float inv = 1.f / dsum;
    float o0 = acc0 * inv + b1[2 * lane];
    float o1 = acc1 * inv + b1[2 * lane + 1];
    o0 = (o0 > 0.f) ? o0 : (__expf(o0) - 1.f);
    o1 = (o1 > 0.f) ? o1 : (__expf(o1) - 1.f);
    rows[warp][2 * lane]     = o0;
    rows[warp][2 * lane + 1] = o1;
    __syncwarp();

    float r0 = 0.f, r1 = 0.f;
    if (lane < 20) {
        int c = 2 * lane;
#pragma unroll 8
        for (int k = 0; k < 64; ++k) {
            float a = rows[warp][k];
            r0 += a * W2s[k * 40 + c];
            r1 += a * W2s[k * 40 + c + 1];
        }
    }
    float ps = 0.f, pd = 0.f;
    if (lane < 20) {
        ps = r0 * sa[2 * lane] + r1 * sa[2 * lane + 1];
        pd = r0 * sd[2 * lane] + r1 * sd[2 * lane + 1];
        g_h2h[(size_t)d * 20 + lane] = __floats2half2_rn(r0, r1);
    }
#pragma unroll
    for (int o = 16; o; o >>= 1) {
        ps += __shfl_xor_sync(FULLM, ps, o);
        pd += __shfl_xor_sync(FULLM, pd, o);
    }
    if (lane == 0) { g_a2s[d] = ps; g_a2d[d] = pd; }
}

// -------- layer-2 agg (shfl-indexed, 4-unroll) + bias + log_softmax ----------
__global__ void k_agg2(const float* __restrict__ b2, float* __restrict__ out, int N) {
    int warp = threadIdx.x >> 5, lane = threadIdx.x & 31;
    int d = blockIdx.x * 8 + warp;
    if (d >= N) return;
    int rs = (d == 0) ? 0 : __ldg(&g_rowptr[d - 1]);
    int re = __ldg(&g_rowptr[d]);
    float adst = g_a2d[d];
    bool act = (lane < 20);

    float wsum = 0.f, acc0 = 0.f, acc1 = 0.f;
    for (int base = rs; base < re; base += 32) {
        int cnt = re - base; if (cnt > 32) cnt = 32;
        int nidx = __ldg(&g_csr[base + ((lane < cnt) ? lane : 0)]);
        int j = 0;
        for (; j + 3 < cnt; j += 4) {
            int s0 = __shfl_sync(FULLM, nidx, j);
            int s1 = __shfl_sync(FULLM, nidx, j + 1);
            int s2 = __shfl_sync(FULLM, nidx, j + 2);
            int s3 = __shfl_sync(FULLM, nidx, j + 3);
            float e0 = __ldg(&g_a2s[s0]) + adst;
            float e1 = __ldg(&g_a2s[s1]) + adst;
            float e2 = __ldg(&g_a2s[s2]) + adst;
            float e3 = __ldg(&g_a2s[s3]) + adst;
            float2 f0, f1, f2, f3;
            if (act) {
                f0 = __half22float2(__ldg(&g_h2h[(size_t)s0 * 20 + lane]));
                f1 = __half22float2(__ldg(&g_h2h[(size_t)s1 * 20 + lane]));
                f2 = __half22float2(__ldg(&g_h2h[(size_t)s2 * 20 + lane]));
                f3 = __half22float2(__ldg(&g_h2h[(size_t)s3 * 20 + lane]));
            }
            e0 = (e0 > 0.f) ? e0 : 0.2f * e0;
            e1 = (e1 > 0.f) ? e1 : 0.2f * e1;
            e2 = (e2 > 0.f) ? e2 : 0.2f * e2;
            e3 = (e3 > 0.f) ? e3 : 0.2f * e3;
            float w0 = __expf(e0), w1 = __expf(e1), w2 = __expf(e2), w3 = __expf(e3);
            wsum += (w0 + w1) + (w2 + w3);
            if (act) {
                acc0 += w0 * f0.x + w1 * f1.x + w2 * f2.x + w3 * f3.x;
                acc1 += w0 * f0.y + w1 * f1.y + w2 * f2.y + w3 * f3.y;
            }
        }
        for (; j < cnt; ++j) {
            int s = __shfl_sync(FULLM, nidx, j);
            float e = __ldg(&g_a2s[s]) + adst;
            e = (e > 0.f) ? e : 0.2f * e;
            float w = __expf(e);
            wsum += w;
            if (act) {
                float2 f = __half22float2(__ldg(&g_h2h[(size_t)s * 20 + lane]));
                acc0 += w * f.x;
                acc1 += w * f.y;
            }
        }
    }
    float inv = 1.f / wsum;
    float v0 = act ? (acc0 * inv + b2[2 * lane]) : -BIGF;
    float v1 = act ? (acc1 * inv + b2[2 * lane + 1]) : -BIGF;

    float mm = fmaxf(v0, v1);
    for (int o = 16; o; o >>= 1) mm = fmaxf(mm, __shfl_xor_sync(FULLM, mm, o));
    float se = act ? (__expf(v0 - mm) + __expf(v1 - mm)) : 0.f;
    for (int o = 16; o; o >>= 1) se += __shfl_xor_sync(FULLM, se, o);
    float ls = mm + logf(se);
    if (act)
        *(float2*)&out[(size_t)d * 40 + 2 * lane] = make_float2(v0 - ls, v1 - ls);
}

// ---------------- launch ----------------
extern "C" void kernel_launch(void* const* d_in, const int* in_sizes, int n_in,
                              void* d_out, int out_size) {
    const float* x   = (const float*)d_in[0];
    const void*  ei  = d_in[1];
    const float* W1  = (const float*)d_in[2];
    const float* as1 = (const float*)d_in[3];
    const float* ad1 = (const float*)d_in[4];
    const float* b1  = (const float*)d_in[5];
    const float* W2  = (const float*)d_in[6];
    const float* as2 = (const float*)d_in[7];
    const float* ad2 = (const float*)d_in[8];
    const float* b2  = (const float*)d_in[9];
    float* out = (float*)d_out;

    int N = in_sizes[0] / 128;
    int E = in_sizes[1] / 2;
    int NB = (N + 1023) / 1024;

    static cudaStream_t s2 = nullptr;
    static cudaEvent_t evFork = nullptr, evJoin = nullptr;
    if (!s2) {
        cudaStreamCreateWithFlags(&s2, cudaStreamNonBlocking);
        cudaEventCreateWithFlags(&evFork, cudaEventDisableTiming);
        cudaEventCreateWithFlags(&evJoin, cudaEventDisableTiming);
    }

    cudaEventRecord(evFork, 0);
    cudaStreamWaitEvent(s2, evFork, 0);
    k_gemm1<<<(N + 127) / 128, 256, 0, s2>>>(x, W1, as1, ad1, N);
    cudaEventRecord(evJoin, s2);

    k_initdet<<<(N + 255) / 256, 256>>>((const unsigned*)ei, N);
    k_hist<<<(E / 2 + 255) / 256, 256>>>(ei, E);
    k_scan<<<NB, 1024>>>(N, NB);
    k_scatter<<<(E + N + 255) / 256, 256>>>(ei, E, N);

    cudaStreamWaitEvent(0, evJoin, 0);
    k_agg1g2<<<(N + 7) / 8, 256>>>(b1, W2, as2, ad2, N);
    k_agg2<<<(N + 7) / 8, 256>>>(b2, out, N);
}